// round 15
// baseline (speedup 1.0000x reference)
#include <cuda_runtime.h>
#include <cuda_bf16.h>
#include <math.h>

#define GRID 32
#define NGRID3 (GRID*GRID*GRID)
#define NROWS 48          // tri_table rows; output is (32768, 48)
#define BS 256            // threads per block
#define LANES 128         // packed point-pairs per block (256 points)
#define HALF_ROWS (NROWS/2)

typedef unsigned long long u64;
#define SGNMASK 0x8000000080000000ULL

// ---- packed f32x2 primitives (Blackwell FFMA2 path; per-half bit-identical
// ---- to the corresponding scalar IEEE ops) ----
__device__ __forceinline__ u64 pk2(float lo, float hi) {
    u64 r; asm("mov.b64 %0, {%1, %2};" : "=l"(r) : "f"(lo), "f"(hi)); return r;
}
__device__ __forceinline__ void upk2(u64 v, float& lo, float& hi) {
    asm("mov.b64 {%0, %1}, %2;" : "=f"(lo), "=f"(hi) : "l"(v));
}
__device__ __forceinline__ u64 padd(u64 a, u64 b) {
    u64 r; asm("add.rn.f32x2 %0, %1, %2;" : "=l"(r) : "l"(a), "l"(b)); return r;
}
__device__ __forceinline__ u64 pmul(u64 a, u64 b) {
    u64 r; asm("mul.rn.f32x2 %0, %1, %2;" : "=l"(r) : "l"(a), "l"(b)); return r;
}
__device__ __forceinline__ u64 pfma(u64 a, u64 b, u64 c) {
    u64 r; asm("fma.rn.f32x2 %0, %1, %2, %3;" : "=l"(r) : "l"(a), "l"(b), "l"(c)); return r;
}
// a - b, exactly (fma with -1: product exact, single rounding == sub.rn)
__device__ __forceinline__ u64 psub(u64 a, u64 b) {
    const u64 NEG1 = 0xBF800000BF800000ULL;
    return pfma(b, NEG1, a);
}
// Non-contracted dot, left-to-right (matches XLA / scalar dot3x bitwise)
__device__ __forceinline__ u64 pdot(u64 ux, u64 uy, u64 uz, u64 vx, u64 vy, u64 vz) {
    return padd(padd(pmul(ux, vx), pmul(uy, vy)), pmul(uz, vz));
}

__device__ __forceinline__ float sdiv(float n, float d) {
    // matches jnp: n / where(|d| > 1e-12, d, 1e-12)
    d = (fabsf(d) > 1e-12f) ? d : 1e-12f;
    return __fdividef(n, d);
}

// Scalar region resolution (sequential jnp.where chain, last-satisfied wins).
// All operands arrive bit-exact vs the reference computation.
__device__ __forceinline__ void region_vw(
    float d1, float d2, float d3, float d4, float d5, float d6,
    float va, float vb, float vc, float d43, float d56,
    float den_ab, float den_ac, float den_bc, float den_in,
    float& v, float& w)
{
    float v_ab = sdiv(d1, den_ab);
    float w_ac = sdiv(d2, den_ac);
    float w_bc = sdiv(d43, den_bc);
    float inv  = sdiv(1.0f, den_in);
    v = __fmul_rn(vb, inv);
    w = __fmul_rn(vc, inv);

    bool r_bc = (va <= 0.0f) && (d43 >= 0.0f) && (d56 >= 0.0f);
    float omw = 1.0f - w_bc;
    v = r_bc ? omw : v;    w = r_bc ? w_bc : w;

    bool r_ac = (vb <= 0.0f) && (d2 >= 0.0f) && (d6 <= 0.0f);
    v = r_ac ? 0.0f : v;   w = r_ac ? w_ac : w;

    bool r_c = (d6 >= 0.0f) && (d5 <= d6);
    v = r_c ? 0.0f : v;    w = r_c ? 1.0f : w;

    bool r_ab = (vc <= 0.0f) && (d1 >= 0.0f) && (d3 <= 0.0f);
    v = r_ab ? v_ab : v;   w = r_ab ? 0.0f : w;

    bool r_b = (d3 >= 0.0f) && (d4 <= d3);
    v = r_b ? 1.0f : v;    w = r_b ? 0.0f : w;

    bool r_a = (d1 <= 0.0f) && (d2 <= 0.0f);
    v = r_a ? 0.0f : v;    w = r_a ? 0.0f : w;
}

__global__ void zero_out_kernel(float* __restrict__ out, int n) {
    int i = blockIdx.x * blockDim.x + threadIdx.x;
    if (i < n) out[i] = 0.0f;
}

__global__ __launch_bounds__(BS, 4)
void ptd_kernel(const float* __restrict__ offset,
                const float* __restrict__ points,
                const int*   __restrict__ tri_table,
                float*       __restrict__ out,
                int npts)
{
    // Edge vertices for the block's 128 lanes (256 pts): float2 per lane.
    __shared__ float2 s_v[36 * LANES];
    __shared__ float2 s_p[3 * LANES];      // local coords, lane-packed
    __shared__ int    s_cid[2 * LANES];    // cell id per point
    __shared__ int    s_tri[NROWS * 9];    // vertex indices pre-scaled

    const int tid = threadIdx.x;
    for (int k = tid; k < NROWS * 9; k += BS) s_tri[k] = tri_table[k] * LANES;

    // ---- setup: each thread prepares exactly ONE point ----
    // point index: threads 0..127 -> lane .x (pts blk*256+0..127),
    //              threads 128..255 -> lane .y (pts blk*256+128..255)
    const int gi = blockIdx.x * (2 * LANES) + tid;
    const bool gvalid = (gi < npts);
    const int li = gvalid ? gi : 0;

    float px = points[3*li+0], py = points[3*li+1], pz = points[3*li+2];
    int cx = min(max(__float2int_rd(px), 0), GRID-1);
    int cy = min(max(__float2int_rd(py), 0), GRID-1);
    int cz = min(max(__float2int_rd(pz), 0), GRID-1);
    float lx = px - (float)cx, ly = py - (float)cy, lz = pz - (float)cz;

    const int lane = tid & (LANES - 1);
    const int half = tid >> 7;             // 0 = .x, 1 = .y

    float* s_pf = reinterpret_cast<float*>(s_p);
    s_pf[(0*LANES + lane)*2 + half] = lx;
    s_pf[(1*LANES + lane)*2 + half] = ly;
    s_pf[(2*LANES + lane)*2 + half] = lz;
    s_cid[tid] = (cx * GRID + cy) * GRID + cz;

    // Edge tables (compile-time folded): vert[e] = base + unit(axis)*t
    constexpr float hbx[12] = {0,1,0,0,0,1,0,0,0,1,1,0};
    constexpr float hby[12] = {0,0,1,0,0,0,1,0,0,0,1,1};
    constexpr float hbz[12] = {0,0,0,0,1,1,1,1,0,0,0,0};
    constexpr int   hax[12] = {0,1,0,1,0,1,0,1,2,2,2,2};
    constexpr int   hgo[12] = {0, 37026, 33, 35937, 1, 37027, 34, 35938,
                               71874, 72963, 72996, 71907};

    float* s_vf = reinterpret_cast<float*>(s_v);
    const int gbase = (cx * 33 + cy) * 33 + cz;
    #pragma unroll
    for (int e = 0; e < 12; e++) {
        float t = __ldg(&offset[gbase + hgo[e]]);
        s_vf[((0*12 + e)*LANES + lane)*2 + half] = (hax[e]==0) ? t : hbx[e];
        s_vf[((1*12 + e)*LANES + lane)*2 + half] = (hax[e]==1) ? t : hby[e];
        s_vf[((2*12 + e)*LANES + lane)*2 + half] = (hax[e]==2) ? t : hbz[e];
    }
    __syncthreads();

    // ---- main loop: thread handles its lane for one half of the rows ----
    const u64* __restrict__ s_vu = reinterpret_cast<const u64*>(s_v);
    const u64* __restrict__ s_pu = reinterpret_cast<const u64*>(s_p);

    const u64 ppx = s_pu[0*LANES + lane];
    const u64 ppy = s_pu[1*LANES + lane];
    const u64 ppz = s_pu[2*LANES + lane];

    const int piA = blockIdx.x * (2 * LANES) + lane;          // lo half pt
    const int piB = piA + LANES;                              // hi half pt
    const bool validA = (piA < npts);
    const bool validB = (piB < npts);
    float* rowA = out + (size_t)s_cid[lane]         * NROWS;
    float* rowB = out + (size_t)s_cid[lane + LANES] * NROWS;

    const int r0 = half * HALF_ROWS;
    for (int tr = r0; tr < r0 + HALF_ROWS; tr++) {
        float dminA = INFINITY, dminB = INFINITY;
        #pragma unroll
        for (int j = 0; j < 3; j++) {
            const int base = tr * 9 + j * 3;
            const int o0 = s_tri[base + 0] + lane;
            const int o1 = s_tri[base + 1] + lane;
            const int o2 = s_tri[base + 2] + lane;

            u64 ax = s_vu[o0], ay = s_vu[o0 + 12*LANES], az = s_vu[o0 + 24*LANES];
            u64 bx = s_vu[o1], by = s_vu[o1 + 12*LANES], bz = s_vu[o1 + 24*LANES];
            u64 cx2 = s_vu[o2], cy2 = s_vu[o2 + 12*LANES], cz2 = s_vu[o2 + 24*LANES];

            // packed geometry (per-half bitwise == reference scalar ops)
            u64 abx = psub(bx, ax), aby = psub(by, ay), abz = psub(bz, az);
            u64 acx = psub(cx2, ax), acy = psub(cy2, ay), acz = psub(cz2, az);
            u64 apx = psub(ppx, ax), apy = psub(ppy, ay), apz = psub(ppz, az);
            u64 bpx = psub(ppx, bx), bpy = psub(ppy, by), bpz = psub(ppz, bz);
            u64 cpx = psub(ppx, cx2), cpy = psub(ppy, cy2), cpz = psub(ppz, cz2);

            u64 d1 = pdot(abx, aby, abz, apx, apy, apz);
            u64 d2 = pdot(acx, acy, acz, apx, apy, apz);
            u64 d3 = pdot(abx, aby, abz, bpx, bpy, bpz);
            u64 d4 = pdot(acx, acy, acz, bpx, bpy, bpz);
            u64 d5 = pdot(abx, aby, abz, cpx, cpy, cpz);
            u64 d6 = pdot(acx, acy, acz, cpx, cpy, cpz);

            // separate mul then sub: exact cancellation on degenerate tris
            u64 vcp = psub(pmul(d1, d4), pmul(d3, d2));
            u64 vbp = psub(pmul(d5, d2), pmul(d1, d6));
            u64 vap = psub(pmul(d3, d6), pmul(d5, d4));

            u64 d43 = psub(d4, d3);
            u64 d56 = psub(d5, d6);
            u64 den_ab = psub(d1, d3);
            u64 den_ac = psub(d2, d6);
            u64 den_bc = padd(d43, d56);
            u64 den_in = padd(padd(vap, vbp), vcp);

            // unpack for scalar region logic
            float d1A,d1B,d2A,d2B,d3A,d3B,d4A,d4B,d5A,d5B,d6A,d6B;
            float vaA,vaB,vbA,vbB,vcA,vcB,d43A,d43B,d56A,d56B;
            float dabA,dabB,dacA,dacB,dbcA,dbcB,dinA,dinB;
            upk2(d1,d1A,d1B); upk2(d2,d2A,d2B); upk2(d3,d3A,d3B);
            upk2(d4,d4A,d4B); upk2(d5,d5A,d5B); upk2(d6,d6A,d6B);
            upk2(vap,vaA,vaB); upk2(vbp,vbA,vbB); upk2(vcp,vcA,vcB);
            upk2(d43,d43A,d43B); upk2(d56,d56A,d56B);
            upk2(den_ab,dabA,dabB); upk2(den_ac,dacA,dacB);
            upk2(den_bc,dbcA,dbcB); upk2(den_in,dinA,dinB);

            float vA, wA, vB, wB;
            region_vw(d1A,d2A,d3A,d4A,d5A,d6A, vaA,vbA,vcA, d43A,d56A,
                      dabA,dacA,dbcA,dinA, vA, wA);
            region_vw(d1B,d2B,d3B,d4B,d5B,d6B, vaB,vbB,vcB, d43B,d56B,
                      dabB,dacB,dbcB,dinB, vB, wB);

            // packed closest-point & distance (ulp-level reassociation; benign)
            u64 nv = pk2(vA, vB) ^ SGNMASK;
            u64 nw = pk2(wA, wB) ^ SGNMASK;
            u64 pqx = pfma(acx, nw, pfma(abx, nv, apx));
            u64 pqy = pfma(acy, nw, pfma(aby, nv, apy));
            u64 pqz = pfma(acz, nw, pfma(abz, nv, apz));
            u64 dd = pfma(pqz, pqz, pfma(pqy, pqy, pmul(pqx, pqx)));

            float dA, dB;
            upk2(dd, dA, dB);
            dminA = fminf(dminA, dA);
            dminB = fminf(dminB, dB);
        }
        if (validA) atomicAdd(&rowA[tr], dminA);
        if (validB) atomicAdd(&rowB[tr], dminB);
    }
}

extern "C" void kernel_launch(void* const* d_in, const int* in_sizes, int n_in,
                              void* d_out, int out_size) {
    const float* offset    = (const float*)d_in[0];  // (3,33,33,33)
    const float* points    = (const float*)d_in[1];  // (N,3)
    const int*   tri_table = (const int*)d_in[2];    // (48,3,3)
    float* out = (float*)d_out;                      // (32768, 48)

    const int npts = in_sizes[1] / 3;
    const int nblk = (npts + 2*LANES - 1) / (2*LANES);

    zero_out_kernel<<<(out_size + 255) / 256, 256>>>(out, out_size);
    ptd_kernel<<<nblk, BS>>>(offset, points, tri_table, out, npts);
}

// round 16
// speedup vs baseline: 1.1547x; 1.1547x over previous
#include <cuda_runtime.h>
#include <cuda_bf16.h>
#include <math.h>

#define GRID 32
#define NGRID3 (GRID*GRID*GRID)
#define NROWS 48          // tri_table rows; output is (32768, 48)
#define BS 128            // threads per block (4 warps)
#define LANES 64          // packed point-pairs per block (128 points)
#define HALF_ROWS (NROWS/2)

typedef unsigned long long u64;
#define SGNMASK 0x8000000080000000ULL

// ---- packed f32x2 primitives (Blackwell FFMA2 path; per-half bit-identical
// ---- to the corresponding scalar IEEE ops) ----
__device__ __forceinline__ u64 pk2(float lo, float hi) {
    u64 r; asm("mov.b64 %0, {%1, %2};" : "=l"(r) : "f"(lo), "f"(hi)); return r;
}
__device__ __forceinline__ void upk2(u64 v, float& lo, float& hi) {
    asm("mov.b64 {%0, %1}, %2;" : "=f"(lo), "=f"(hi) : "l"(v));
}
__device__ __forceinline__ u64 padd(u64 a, u64 b) {
    u64 r; asm("add.rn.f32x2 %0, %1, %2;" : "=l"(r) : "l"(a), "l"(b)); return r;
}
__device__ __forceinline__ u64 pmul(u64 a, u64 b) {
    u64 r; asm("mul.rn.f32x2 %0, %1, %2;" : "=l"(r) : "l"(a), "l"(b)); return r;
}
__device__ __forceinline__ u64 pfma(u64 a, u64 b, u64 c) {
    u64 r; asm("fma.rn.f32x2 %0, %1, %2, %3;" : "=l"(r) : "l"(a), "l"(b), "l"(c)); return r;
}
// a - b, exactly (fma with -1: product exact, single rounding == sub.rn)
__device__ __forceinline__ u64 psub(u64 a, u64 b) {
    const u64 NEG1 = 0xBF800000BF800000ULL;
    return pfma(b, NEG1, a);
}
// Non-contracted dot, left-to-right (matches XLA / scalar dot3x bitwise)
__device__ __forceinline__ u64 pdot(u64 ux, u64 uy, u64 uz, u64 vx, u64 vy, u64 vz) {
    return padd(padd(pmul(ux, vx), pmul(uy, vy)), pmul(uz, vz));
}

__device__ __forceinline__ float sdiv(float n, float d) {
    // matches jnp: n / where(|d| > 1e-12, d, 1e-12)
    d = (fabsf(d) > 1e-12f) ? d : 1e-12f;
    return __fdividef(n, d);
}

// Scalar region resolution (sequential jnp.where chain, last-satisfied wins).
// All operands arrive bit-exact vs the reference computation.
__device__ __forceinline__ void region_vw(
    float d1, float d2, float d3, float d4, float d5, float d6,
    float va, float vb, float vc, float d43, float d56,
    float den_ab, float den_ac, float den_bc, float den_in,
    float& v, float& w)
{
    float v_ab = sdiv(d1, den_ab);
    float w_ac = sdiv(d2, den_ac);
    float w_bc = sdiv(d43, den_bc);
    float inv  = sdiv(1.0f, den_in);
    v = __fmul_rn(vb, inv);
    w = __fmul_rn(vc, inv);

    bool r_bc = (va <= 0.0f) && (d43 >= 0.0f) && (d56 >= 0.0f);
    float omw = 1.0f - w_bc;
    v = r_bc ? omw : v;    w = r_bc ? w_bc : w;

    bool r_ac = (vb <= 0.0f) && (d2 >= 0.0f) && (d6 <= 0.0f);
    v = r_ac ? 0.0f : v;   w = r_ac ? w_ac : w;

    bool r_c = (d6 >= 0.0f) && (d5 <= d6);
    v = r_c ? 0.0f : v;    w = r_c ? 1.0f : w;

    bool r_ab = (vc <= 0.0f) && (d1 >= 0.0f) && (d3 <= 0.0f);
    v = r_ab ? v_ab : v;   w = r_ab ? 0.0f : w;

    bool r_b = (d3 >= 0.0f) && (d4 <= d3);
    v = r_b ? 1.0f : v;    w = r_b ? 0.0f : w;

    bool r_a = (d1 <= 0.0f) && (d2 <= 0.0f);
    v = r_a ? 0.0f : v;    w = r_a ? 0.0f : w;
}

__global__ void zero_out_kernel(float* __restrict__ out, int n) {
    int i = blockIdx.x * blockDim.x + threadIdx.x;
    if (i < n) out[i] = 0.0f;
}

__global__ __launch_bounds__(BS, 7)
void ptd_kernel(const float* __restrict__ offset,
                const float* __restrict__ points,
                const int*   __restrict__ tri_table,
                float*       __restrict__ out,
                int npts)
{
    // Edge vertices for the block's 64 lanes (128 pts): float2 per lane.
    __shared__ float2 s_v[36 * LANES];
    __shared__ float2 s_p[3 * LANES];      // local coords, lane-packed
    __shared__ int    s_cid[2 * LANES];    // cell id per point
    __shared__ int    s_tri[NROWS * 9];    // vertex indices pre-scaled

    const int tid = threadIdx.x;
    for (int k = tid; k < NROWS * 9; k += BS) s_tri[k] = tri_table[k] * LANES;

    // ---- setup: each thread prepares exactly ONE point ----
    // threads 0..63 -> lane .x (pts blk*128+0..63),
    // threads 64..127 -> lane .y (pts blk*128+64..127)
    const int gi = blockIdx.x * (2 * LANES) + tid;
    const bool gvalid = (gi < npts);
    const int li = gvalid ? gi : 0;

    float px = points[3*li+0], py = points[3*li+1], pz = points[3*li+2];
    int cx = min(max(__float2int_rd(px), 0), GRID-1);
    int cy = min(max(__float2int_rd(py), 0), GRID-1);
    int cz = min(max(__float2int_rd(pz), 0), GRID-1);
    float lx = px - (float)cx, ly = py - (float)cy, lz = pz - (float)cz;

    const int lane = tid & (LANES - 1);
    const int half = tid >> 6;             // 0 = .x, 1 = .y

    float* s_pf = reinterpret_cast<float*>(s_p);
    s_pf[(0*LANES + lane)*2 + half] = lx;
    s_pf[(1*LANES + lane)*2 + half] = ly;
    s_pf[(2*LANES + lane)*2 + half] = lz;
    s_cid[tid] = (cx * GRID + cy) * GRID + cz;

    // Edge tables (compile-time folded): vert[e] = base + unit(axis)*t
    constexpr float hbx[12] = {0,1,0,0,0,1,0,0,0,1,1,0};
    constexpr float hby[12] = {0,0,1,0,0,0,1,0,0,0,1,1};
    constexpr float hbz[12] = {0,0,0,0,1,1,1,1,0,0,0,0};
    constexpr int   hax[12] = {0,1,0,1,0,1,0,1,2,2,2,2};
    constexpr int   hgo[12] = {0, 37026, 33, 35937, 1, 37027, 34, 35938,
                               71874, 72963, 72996, 71907};

    float* s_vf = reinterpret_cast<float*>(s_v);
    const int gbase = (cx * 33 + cy) * 33 + cz;
    #pragma unroll
    for (int e = 0; e < 12; e++) {
        float t = __ldg(&offset[gbase + hgo[e]]);
        s_vf[((0*12 + e)*LANES + lane)*2 + half] = (hax[e]==0) ? t : hbx[e];
        s_vf[((1*12 + e)*LANES + lane)*2 + half] = (hax[e]==1) ? t : hby[e];
        s_vf[((2*12 + e)*LANES + lane)*2 + half] = (hax[e]==2) ? t : hbz[e];
    }
    __syncthreads();

    // ---- main loop: thread handles its lane for one half of the rows ----
    const u64* __restrict__ s_vu = reinterpret_cast<const u64*>(s_v);
    const u64* __restrict__ s_pu = reinterpret_cast<const u64*>(s_p);

    const u64 ppx = s_pu[0*LANES + lane];
    const u64 ppy = s_pu[1*LANES + lane];
    const u64 ppz = s_pu[2*LANES + lane];

    const int piA = blockIdx.x * (2 * LANES) + lane;          // lo half pt
    const int piB = piA + LANES;                              // hi half pt
    const bool validA = (piA < npts);
    const bool validB = (piB < npts);
    float* rowA = out + (size_t)s_cid[lane]         * NROWS;
    float* rowB = out + (size_t)s_cid[lane + LANES] * NROWS;

    const int r0 = half * HALF_ROWS;
    for (int tr = r0; tr < r0 + HALF_ROWS; tr++) {
        float dminA = INFINITY, dminB = INFINITY;
        #pragma unroll
        for (int j = 0; j < 3; j++) {
            const int base = tr * 9 + j * 3;
            const int o0 = s_tri[base + 0] + lane;
            const int o1 = s_tri[base + 1] + lane;
            const int o2 = s_tri[base + 2] + lane;

            u64 ax = s_vu[o0], ay = s_vu[o0 + 12*LANES], az = s_vu[o0 + 24*LANES];
            u64 bx = s_vu[o1], by = s_vu[o1 + 12*LANES], bz = s_vu[o1 + 24*LANES];
            u64 cx2 = s_vu[o2], cy2 = s_vu[o2 + 12*LANES], cz2 = s_vu[o2 + 24*LANES];

            // packed geometry (per-half bitwise == reference scalar ops)
            u64 abx = psub(bx, ax), aby = psub(by, ay), abz = psub(bz, az);
            u64 acx = psub(cx2, ax), acy = psub(cy2, ay), acz = psub(cz2, az);
            u64 apx = psub(ppx, ax), apy = psub(ppy, ay), apz = psub(ppz, az);
            u64 bpx = psub(ppx, bx), bpy = psub(ppy, by), bpz = psub(ppz, bz);
            u64 cpx = psub(ppx, cx2), cpy = psub(ppy, cy2), cpz = psub(ppz, cz2);

            u64 d1 = pdot(abx, aby, abz, apx, apy, apz);
            u64 d2 = pdot(acx, acy, acz, apx, apy, apz);
            u64 d3 = pdot(abx, aby, abz, bpx, bpy, bpz);
            u64 d4 = pdot(acx, acy, acz, bpx, bpy, bpz);
            u64 d5 = pdot(abx, aby, abz, cpx, cpy, cpz);
            u64 d6 = pdot(acx, acy, acz, cpx, cpy, cpz);

            // separate mul then sub: exact cancellation on degenerate tris
            u64 vcp = psub(pmul(d1, d4), pmul(d3, d2));
            u64 vbp = psub(pmul(d5, d2), pmul(d1, d6));
            u64 vap = psub(pmul(d3, d6), pmul(d5, d4));

            u64 d43 = psub(d4, d3);
            u64 d56 = psub(d5, d6);
            u64 den_ab = psub(d1, d3);
            u64 den_ac = psub(d2, d6);
            u64 den_bc = padd(d43, d56);
            u64 den_in = padd(padd(vap, vbp), vcp);

            // unpack for scalar region logic
            float d1A,d1B,d2A,d2B,d3A,d3B,d4A,d4B,d5A,d5B,d6A,d6B;
            float vaA,vaB,vbA,vbB,vcA,vcB,d43A,d43B,d56A,d56B;
            float dabA,dabB,dacA,dacB,dbcA,dbcB,dinA,dinB;
            upk2(d1,d1A,d1B); upk2(d2,d2A,d2B); upk2(d3,d3A,d3B);
            upk2(d4,d4A,d4B); upk2(d5,d5A,d5B); upk2(d6,d6A,d6B);
            upk2(vap,vaA,vaB); upk2(vbp,vbA,vbB); upk2(vcp,vcA,vcB);
            upk2(d43,d43A,d43B); upk2(d56,d56A,d56B);
            upk2(den_ab,dabA,dabB); upk2(den_ac,dacA,dacB);
            upk2(den_bc,dbcA,dbcB); upk2(den_in,dinA,dinB);

            float vA, wA, vB, wB;
            region_vw(d1A,d2A,d3A,d4A,d5A,d6A, vaA,vbA,vcA, d43A,d56A,
                      dabA,dacA,dbcA,dinA, vA, wA);
            region_vw(d1B,d2B,d3B,d4B,d5B,d6B, vaB,vbB,vcB, d43B,d56B,
                      dabB,dacB,dbcB,dinB, vB, wB);

            // packed closest-point & distance (ulp-level reassociation; benign)
            u64 nv = pk2(vA, vB) ^ SGNMASK;
            u64 nw = pk2(wA, wB) ^ SGNMASK;
            u64 pqx = pfma(acx, nw, pfma(abx, nv, apx));
            u64 pqy = pfma(acy, nw, pfma(aby, nv, apy));
            u64 pqz = pfma(acz, nw, pfma(abz, nv, apz));
            u64 dd = pfma(pqz, pqz, pfma(pqy, pqy, pmul(pqx, pqx)));

            float dA, dB;
            upk2(dd, dA, dB);
            dminA = fminf(dminA, dA);
            dminB = fminf(dminB, dB);
        }
        if (validA) atomicAdd(&rowA[tr], dminA);
        if (validB) atomicAdd(&rowB[tr], dminB);
    }
}

extern "C" void kernel_launch(void* const* d_in, const int* in_sizes, int n_in,
                              void* d_out, int out_size) {
    const float* offset    = (const float*)d_in[0];  // (3,33,33,33)
    const float* points    = (const float*)d_in[1];  // (N,3)
    const int*   tri_table = (const int*)d_in[2];    // (48,3,3)
    float* out = (float*)d_out;                      // (32768, 48)

    const int npts = in_sizes[1] / 3;
    const int nblk = (npts + 2*LANES - 1) / (2*LANES);

    zero_out_kernel<<<(out_size + 255) / 256, 256>>>(out, out_size);
    ptd_kernel<<<nblk, BS>>>(offset, points, tri_table, out, npts);
}

// round 17
// speedup vs baseline: 1.2444x; 1.0776x over previous
#include <cuda_runtime.h>
#include <cuda_bf16.h>
#include <math.h>

#define GRID 32
#define NGRID3 (GRID*GRID*GRID)
#define NROWS 48          // tri_table rows; output is (32768, 48)
#define BS 128            // threads per block (4 warps)
#define LANES 64          // packed point-pairs per block (128 points)
#define HALF_ROWS (NROWS/2)

typedef unsigned long long u64;

// ---- packed f32x2 primitives (Blackwell FFMA2 path; per-half bit-identical
// ---- to the corresponding scalar IEEE ops) ----
__device__ __forceinline__ u64 padd(u64 a, u64 b) {
    u64 r; asm("add.rn.f32x2 %0, %1, %2;" : "=l"(r) : "l"(a), "l"(b)); return r;
}
__device__ __forceinline__ u64 pmul(u64 a, u64 b) {
    u64 r; asm("mul.rn.f32x2 %0, %1, %2;" : "=l"(r) : "l"(a), "l"(b)); return r;
}
__device__ __forceinline__ u64 pfma(u64 a, u64 b, u64 c) {
    u64 r; asm("fma.rn.f32x2 %0, %1, %2, %3;" : "=l"(r) : "l"(a), "l"(b), "l"(c)); return r;
}
// a - b, exactly (fma with -1: product exact, single rounding == sub.rn)
__device__ __forceinline__ u64 psub(u64 a, u64 b) {
    const u64 NEG1 = 0xBF800000BF800000ULL;
    return pfma(b, NEG1, a);
}
__device__ __forceinline__ u64 pk2(float lo, float hi) {
    u64 r; asm("mov.b64 %0, {%1, %2};" : "=l"(r) : "f"(lo), "f"(hi)); return r;
}
__device__ __forceinline__ void upk2(u64 v, float& lo, float& hi) {
    asm("mov.b64 {%0, %1}, %2;" : "=f"(lo), "=f"(hi) : "l"(v));
}
// Non-contracted dot, left-to-right (matches XLA / scalar ops bitwise)
__device__ __forceinline__ u64 pdot(u64 ux, u64 uy, u64 uz, u64 vx, u64 vy, u64 vz) {
    return padd(padd(pmul(ux, vx), pmul(uy, vy)), pmul(uz, vz));
}

__device__ __forceinline__ float sdiv(float n, float d) {
    // matches jnp: n / where(|d| > 1e-12, d, 1e-12)
    d = (fabsf(d) > 1e-12f) ? d : 1e-12f;
    return __fdividef(n, d);
}

// Region resolution (sequential jnp.where chain, last-satisfied wins),
// emitting NEGATED (v,w): negations fold into FMUL/div operand modifiers
// (bitwise -(x)), and the q assembly consumes -v,-w directly (p-q form).
// Conditions use the same operand values as before.
__device__ __forceinline__ void region_vw_neg(
    float d1, float d2, float d3, float d4, float d5, float d6,
    float va, float vb, float vc, float d43, float d56,
    float den_ab, float den_ac, float den_bc, float den_in,
    float& nv, float& nw)
{
    float nv_ab = sdiv(-d1, den_ab);    // = -v_ab (sign exact in division)
    float nw_ac = sdiv(-d2, den_ac);    // = -w_ac
    float nw_bc = sdiv(-d43, den_bc);   // = -w_bc
    float inv   = sdiv(1.0f, den_in);
    nv = __fmul_rn(-vb, inv);           // = -(vb*inv) bitwise
    nw = __fmul_rn(-vc, inv);

    bool r_bc = (va <= 0.0f) && (d43 >= 0.0f) && (d56 >= 0.0f);
    float nomw = __fadd_rn(-nw_bc, -1.0f);   // = -(1 - w_bc) bitwise
    nv = r_bc ? nomw  : nv;   nw = r_bc ? nw_bc : nw;

    bool r_ac = (vb <= 0.0f) && (d2 >= 0.0f) && (d6 <= 0.0f);
    nv = r_ac ? 0.0f : nv;    nw = r_ac ? nw_ac : nw;

    bool r_c = (d6 >= 0.0f) && (d5 <= d6);
    nv = r_c ? 0.0f : nv;     nw = r_c ? -1.0f : nw;

    bool r_ab = (vc <= 0.0f) && (d1 >= 0.0f) && (d3 <= 0.0f);
    nv = r_ab ? nv_ab : nv;   nw = r_ab ? 0.0f : nw;

    bool r_b = (d3 >= 0.0f) && (d4 <= d3);
    nv = r_b ? -1.0f : nv;    nw = r_b ? 0.0f : nw;

    bool r_a = (d1 <= 0.0f) && (d2 <= 0.0f);
    nv = r_a ? 0.0f : nv;     nw = r_a ? 0.0f : nw;
}

__global__ void zero_out_kernel(float* __restrict__ out, int n) {
    int i = blockIdx.x * blockDim.x + threadIdx.x;
    if (i < n) out[i] = 0.0f;
}

__global__ __launch_bounds__(BS, 7)
void ptd_kernel(const float* __restrict__ offset,
                const float* __restrict__ points,
                const int*   __restrict__ tri_table,
                float*       __restrict__ out,
                int npts)
{
    // Edge vertices for the block's 64 lanes (128 pts): float2 per lane.
    __shared__ float2 s_v[36 * LANES];
    __shared__ float2 s_p[3 * LANES];      // local coords, lane-packed
    __shared__ int    s_cid[2 * LANES];    // cell id per point
    __shared__ int    s_tri[NROWS * 9];    // vertex indices pre-scaled

    const int tid = threadIdx.x;
    for (int k = tid; k < NROWS * 9; k += BS) s_tri[k] = tri_table[k] * LANES;

    // ---- setup: each thread prepares exactly ONE point ----
    const int gi = blockIdx.x * (2 * LANES) + tid;
    const bool gvalid = (gi < npts);
    const int li = gvalid ? gi : 0;

    float px = points[3*li+0], py = points[3*li+1], pz = points[3*li+2];
    int cx = min(max(__float2int_rd(px), 0), GRID-1);
    int cy = min(max(__float2int_rd(py), 0), GRID-1);
    int cz = min(max(__float2int_rd(pz), 0), GRID-1);
    float lx = px - (float)cx, ly = py - (float)cy, lz = pz - (float)cz;

    const int lane = tid & (LANES - 1);
    const int half = tid >> 6;             // 0 = .x, 1 = .y

    float* s_pf = reinterpret_cast<float*>(s_p);
    s_pf[(0*LANES + lane)*2 + half] = lx;
    s_pf[(1*LANES + lane)*2 + half] = ly;
    s_pf[(2*LANES + lane)*2 + half] = lz;
    s_cid[tid] = (cx * GRID + cy) * GRID + cz;

    // Edge tables (compile-time folded): vert[e] = base + unit(axis)*t
    constexpr float hbx[12] = {0,1,0,0,0,1,0,0,0,1,1,0};
    constexpr float hby[12] = {0,0,1,0,0,0,1,0,0,0,1,1};
    constexpr float hbz[12] = {0,0,0,0,1,1,1,1,0,0,0,0};
    constexpr int   hax[12] = {0,1,0,1,0,1,0,1,2,2,2,2};
    constexpr int   hgo[12] = {0, 37026, 33, 35937, 1, 37027, 34, 35938,
                               71874, 72963, 72996, 71907};

    float* s_vf = reinterpret_cast<float*>(s_v);
    const int gbase = (cx * 33 + cy) * 33 + cz;
    #pragma unroll
    for (int e = 0; e < 12; e++) {
        float t = __ldg(&offset[gbase + hgo[e]]);
        s_vf[((0*12 + e)*LANES + lane)*2 + half] = (hax[e]==0) ? t : hbx[e];
        s_vf[((1*12 + e)*LANES + lane)*2 + half] = (hax[e]==1) ? t : hby[e];
        s_vf[((2*12 + e)*LANES + lane)*2 + half] = (hax[e]==2) ? t : hbz[e];
    }
    __syncthreads();

    // ---- main loop: thread handles its lane for one half of the rows ----
    const u64* __restrict__ s_vu = reinterpret_cast<const u64*>(s_v);
    const u64* __restrict__ s_pu = reinterpret_cast<const u64*>(s_p);

    const u64 ppx = s_pu[0*LANES + lane];
    const u64 ppy = s_pu[1*LANES + lane];
    const u64 ppz = s_pu[2*LANES + lane];

    const int piA = blockIdx.x * (2 * LANES) + lane;          // lo half pt
    const int piB = piA + LANES;                              // hi half pt
    const bool validA = (piA < npts);
    const bool validB = (piB < npts);
    float* rowA = out + (size_t)s_cid[lane]         * NROWS;
    float* rowB = out + (size_t)s_cid[lane + LANES] * NROWS;

    const int r0 = half * HALF_ROWS;
    for (int tr = r0; tr < r0 + HALF_ROWS; tr++) {
        float dminA = INFINITY, dminB = INFINITY;
        #pragma unroll
        for (int j = 0; j < 3; j++) {
            const int base = tr * 9 + j * 3;
            const int o0 = s_tri[base + 0] + lane;
            const int o1 = s_tri[base + 1] + lane;
            const int o2 = s_tri[base + 2] + lane;

            u64 ax = s_vu[o0], ay = s_vu[o0 + 12*LANES], az = s_vu[o0 + 24*LANES];
            u64 bx = s_vu[o1], by = s_vu[o1 + 12*LANES], bz = s_vu[o1 + 24*LANES];
            u64 cx2 = s_vu[o2], cy2 = s_vu[o2 + 12*LANES], cz2 = s_vu[o2 + 24*LANES];

            // packed geometry (per-half bitwise == reference for the
            // quantities that feed conditions/safe-divs where it matters:
            // degenerate triangles cancel to exact +-0, see analysis)
            u64 abx = psub(bx, ax), aby = psub(by, ay), abz = psub(bz, az);
            u64 acx = psub(cx2, ax), acy = psub(cy2, ay), acz = psub(cz2, az);
            u64 apx = psub(ppx, ax), apy = psub(ppy, ay), apz = psub(ppz, az);

            u64 d1  = pdot(abx, aby, abz, apx, apy, apz);
            u64 d2  = pdot(acx, acy, acz, apx, apy, apz);
            u64 Gaa = pdot(abx, aby, abz, abx, aby, abz);
            u64 Gac = pdot(abx, aby, abz, acx, acy, acz);
            u64 Gcc = pdot(acx, acy, acz, acx, acy, acz);
            u64 d3 = psub(d1, Gaa);   // ab.(p-b)
            u64 d4 = psub(d2, Gac);   // ac.(p-b)
            u64 d5 = psub(d1, Gac);   // ab.(p-c)
            u64 d6 = psub(d2, Gcc);   // ac.(p-c)

            // separate mul then sub: exact cancellation on degenerate tris
            u64 vcp = psub(pmul(d1, d4), pmul(d3, d2));
            u64 vbp = psub(pmul(d5, d2), pmul(d1, d6));
            u64 vap = psub(pmul(d3, d6), pmul(d5, d4));

            u64 d43 = psub(d4, d3);
            u64 d56 = psub(d5, d6);
            u64 den_ab = psub(d1, d3);
            u64 den_ac = psub(d2, d6);
            u64 den_bc = padd(d43, d56);
            u64 den_in = padd(padd(vap, vbp), vcp);

            // unpack for scalar region logic
            float d1A,d1B,d2A,d2B,d3A,d3B,d4A,d4B,d5A,d5B,d6A,d6B;
            float vaA,vaB,vbA,vbB,vcA,vcB,d43A,d43B,d56A,d56B;
            float dabA,dabB,dacA,dacB,dbcA,dbcB,dinA,dinB;
            upk2(d1,d1A,d1B); upk2(d2,d2A,d2B); upk2(d3,d3A,d3B);
            upk2(d4,d4A,d4B); upk2(d5,d5A,d5B); upk2(d6,d6A,d6B);
            upk2(vap,vaA,vaB); upk2(vbp,vbA,vbB); upk2(vcp,vcA,vcB);
            upk2(d43,d43A,d43B); upk2(d56,d56A,d56B);
            upk2(den_ab,dabA,dabB); upk2(den_ac,dacA,dacB);
            upk2(den_bc,dbcA,dbcB); upk2(den_in,dinA,dinB);

            float nvA, nwA, nvB, nwB;
            region_vw_neg(d1A,d2A,d3A,d4A,d5A,d6A, vaA,vbA,vcA, d43A,d56A,
                          dabA,dacA,dbcA,dinA, nvA, nwA);
            region_vw_neg(d1B,d2B,d3B,d4B,d5B,d6B, vaB,vbB,vcB, d43B,d56B,
                          dabB,dacB,dbcB,dinB, nvB, nwB);

            // packed p-q & distance (ulp-level reassociation; benign)
            u64 nv = pk2(nvA, nvB);
            u64 nw = pk2(nwA, nwB);
            u64 pqx = pfma(acx, nw, pfma(abx, nv, apx));
            u64 pqy = pfma(acy, nw, pfma(aby, nv, apy));
            u64 pqz = pfma(acz, nw, pfma(abz, nv, apz));
            u64 dd = pfma(pqz, pqz, pfma(pqy, pqy, pmul(pqx, pqx)));

            float dA, dB;
            upk2(dd, dA, dB);
            dminA = fminf(dminA, dA);
            dminB = fminf(dminB, dB);
        }
        if (validA) atomicAdd(&rowA[tr], dminA);
        if (validB) atomicAdd(&rowB[tr], dminB);
    }
}

extern "C" void kernel_launch(void* const* d_in, const int* in_sizes, int n_in,
                              void* d_out, int out_size) {
    const float* offset    = (const float*)d_in[0];  // (3,33,33,33)
    const float* points    = (const float*)d_in[1];  // (N,3)
    const int*   tri_table = (const int*)d_in[2];    // (48,3,3)
    float* out = (float*)d_out;                      // (32768, 48)

    const int npts = in_sizes[1] / 3;
    const int nblk = (npts + 2*LANES - 1) / (2*LANES);

    zero_out_kernel<<<(out_size + 255) / 256, 256>>>(out, out_size);
    ptd_kernel<<<nblk, BS>>>(offset, points, tri_table, out, npts);
}